// round 3
// baseline (speedup 1.0000x reference)
#include <cuda_runtime.h>
#include <cstdint>

typedef unsigned long long ull;

// ---------------- problem constants ----------------
#define NPART 32
#define L0 (2048*1024)           // W1 per-particle len
#define L1 2048                  // b1
#define L2 (256*2048)            // W2
#define L3 256                   // b2
#define SEG_B0 (L0)              // 2097152
#define SEG_B1 (SEG_B0 + L1)     // 2099200
#define SEG_B2 (SEG_B1 + L2)     // 2623488
#define P_TOT  (SEG_B2 + L3)     // 2623744
#define NP     (P_TOT/2)         // 1311872 k-pairs
#define EPSV 0.1f

// ---- gram pipeline ----
#define GCHUNK 128                   // k per chunk (all seg boundaries are /128)
#define NCHUNK (P_TOT/GCHUNK)        // 20498
#define GSTAGES 4
#define GSTAGE_B (32*GCHUNK*4)       // 16384 B per stage
#define NBLK1 148
#define NWARP1 10

// ---- apply pipeline ----
#define ASPAN 256                    // k per span (128 kp); all seg boundaries /256
#define NSPAN (P_TOT/ASPAN)          // 10249 (exact)
#define ASTAGES 3
#define ASTAGE_B (32*ASPAN*4)        // 32768 B per stage
#define NBLK2 296

// ---------------- scratch ----------------
__device__ float  g_Gpart[NBLK1 * NWARP1 * 64];
__device__ float2 g_Ct[1024];        // transposed coef: g_Ct[j*32+i] = (c,c)

__constant__ int c_TBI[NWARP1] = {0,0,0,0,1,1,1,2,2,3};
__constant__ int c_TBJ[NWARP1] = {0,1,2,3,1,2,3,2,3,3};

// ---------------- PTX helpers ----------------
__device__ __forceinline__ void ffma2(ull &d, ull a, ull b) {
    asm("fma.rn.f32x2 %0, %1, %2, %0;" : "+l"(d) : "l"(a), "l"(b));
}
__device__ __forceinline__ void cp16(uint32_t dst, const void* src) {
    asm volatile("cp.async.cg.shared.global [%0], [%1], 16;" :: "r"(dst), "l"(src));
}
__device__ __forceinline__ void cp_commit() {
    asm volatile("cp.async.commit_group;");
}
template<int N> __device__ __forceinline__ void cp_wait() {
    asm volatile("cp.async.wait_group %0;" :: "n"(N));
}

__device__ __forceinline__ const float* seg_base(int k,
        const float* __restrict__ W1, const float* __restrict__ b1,
        const float* __restrict__ W2, const float* __restrict__ b2,
        int &stride, int &kl) {
    if (k < SEG_B0) { stride = L0; kl = k;          return W1; }
    if (k < SEG_B1) { stride = L1; kl = k - SEG_B0; return b1; }
    if (k < SEG_B2) { stride = L2; kl = k - SEG_B1; return W2; }
    stride = L3; kl = k - SEG_B2; return b2;
}

// ---------------- pass 1: Gram, cp.async-pipelined SYRK ----------------
__global__ __launch_bounds__(320, 1)
void gram_kernel(const float* __restrict__ W1, const float* __restrict__ b1,
                 const float* __restrict__ W2, const float* __restrict__ b2) {
    extern __shared__ char sm[];
    const uint32_t sb32 = (uint32_t)__cvta_generic_to_shared(sm);
    const int tid  = threadIdx.x;
    const int w    = tid >> 5;
    const int lane = tid & 31;
    const int bi = c_TBI[w], bj = c_TBJ[w];

    const int per = NCHUNK / NBLK1, rem = NCHUNK % NBLK1;
    const int b   = blockIdx.x;
    const int c0  = b * per + (b < rem ? b : rem);
    const int cnt = per + (b < rem ? 1 : 0);

    ull acc[64];
#pragma unroll
    for (int p = 0; p < 64; p++) acc[p] = 0ull;

    // producer: stage chunk c into buffer s (1024 x 16B)
    auto load_stage = [&](int c, int s) {
        const int k0 = c * GCHUNK;
        int stride, kl;
        const float* base = seg_base(k0, W1, b1, W2, b2, stride, kl);
        const uint32_t dst0 = sb32 + s * GSTAGE_B;
#pragma unroll
        for (int i = 0; i < 4; i++) {
            int f = tid + i * 320;
            if (f < 1024) {
                int row = f >> 5, c16 = f & 31;
                cp16(dst0 + f * 16, base + (size_t)row * stride + kl + c16 * 4);
            }
        }
    };

    // prologue: stages 0..2
#pragma unroll
    for (int s = 0; s < GSTAGES - 1; s++) {
        if (s < cnt) load_stage(c0 + s, s);
        cp_commit();
    }

    for (int it = 0; it < cnt; it++) {
        cp_wait<GSTAGES - 2>();
        __syncthreads();
        if (it + GSTAGES - 1 < cnt) load_stage(c0 + it + GSTAGES - 1, (it + GSTAGES - 1) & 3);
        cp_commit();

        const char* tb = sm + (it & 3) * GSTAGE_B;
        ulonglong2 av[8];
#pragma unroll
        for (int r = 0; r < 8; r++)
            av[r] = *reinterpret_cast<const ulonglong2*>(tb + (bi * 8 + r) * 512 + lane * 16);
#pragma unroll
        for (int q = 0; q < 8; q++) {
            ulonglong2 bv = *reinterpret_cast<const ulonglong2*>(tb + (bj * 8 + q) * 512 + lane * 16);
#pragma unroll
            for (int r = 0; r < 8; r++) {
                ffma2(acc[r * 8 + q], av[r].x, bv.x);
                ffma2(acc[r * 8 + q], av[r].y, bv.y);
            }
        }
    }

    // reduce across lanes, write partials
#pragma unroll
    for (int p = 0; p < 64; p++) {
        float v = __uint_as_float((unsigned)acc[p]) +
                  __uint_as_float((unsigned)(acc[p] >> 32));
        v += __shfl_xor_sync(0xffffffffu, v, 16);
        v += __shfl_xor_sync(0xffffffffu, v, 8);
        v += __shfl_xor_sync(0xffffffffu, v, 4);
        v += __shfl_xor_sync(0xffffffffu, v, 2);
        v += __shfl_xor_sync(0xffffffffu, v, 1);
        if (lane == 0) g_Gpart[(b * NWARP1 + w) * 64 + p] = v;
    }
}

// ---------------- pass 1b: reduce partials -> K -> coefficient table ----------------
__global__ __launch_bounds__(1024, 1)
void coef_kernel() {
    __shared__ float Gs[32][32];
    __shared__ float Ks[32][33];
    __shared__ float Ssh[32];
    const int tid = threadIdx.x;

    if (tid < NWARP1 * 64) {
        float s0 = 0.f, s1 = 0.f, s2 = 0.f, s3 = 0.f;
#pragma unroll 1
        for (int bb = 0; bb < NBLK1; bb += 4) {
            s0 += g_Gpart[(bb + 0) * (NWARP1 * 64) + tid];
            s1 += g_Gpart[(bb + 1) * (NWARP1 * 64) + tid];
            s2 += g_Gpart[(bb + 2) * (NWARP1 * 64) + tid];
            s3 += g_Gpart[(bb + 3) * (NWARP1 * 64) + tid];
        }
        float s = (s0 + s1) + (s2 + s3);
        int w = tid / 64, pr = tid % 64, r = pr / 8, q = pr % 8;
        Gs[c_TBI[w] * 8 + r][c_TBJ[w] * 8 + q] = s;
    }
    __syncthreads();
    {
        int i = tid >> 5, j = tid & 31;
        if ((i >> 3) > (j >> 3)) Gs[i][j] = Gs[j][i];
    }
    __syncthreads();
    {
        int i = tid >> 5, j = tid & 31;
        float d2 = Gs[i][i] + Gs[j][j] - 2.f * Gs[i][j];
        d2 = fmaxf(d2, 0.f);
        Ks[i][j] = expf(-0.5f * d2);
    }
    __syncthreads();
    if (tid < 32) {
        float s = 0.f;
        for (int j = 1; j < 32; j++) s += Ks[tid][j];
        Ssh[tid] = s;
    }
    __syncthreads();
    {
        int i = tid >> 5, j = tid & 31;
        float v = (j >= 1) ? (EPSV / (float)NPART) * Ks[i][j] : 0.f;
        if (j == i) v += 1.f - 3.f * EPSV * Ssh[i] / (float)NPART;
        g_Ct[j * 32 + i] = make_float2(v, v);   // transposed + duplicated
    }
}

// ---------------- pass 2: out = C @ theta, cp.async-pipelined ----------------
__global__ __launch_bounds__(256, 2)
void apply_kernel(const float* __restrict__ W1, const float* __restrict__ b1,
                  const float* __restrict__ W2, const float* __restrict__ b2,
                  float* __restrict__ out) {
    extern __shared__ char sm[];
    const uint32_t sb32 = (uint32_t)__cvta_generic_to_shared(sm);
    ull* cts = reinterpret_cast<ull*>(sm + ASTAGES * ASTAGE_B);
    const int tid = threadIdx.x;

    // stage coefficient table
    const ull* ctg = reinterpret_cast<const ull*>(g_Ct);
    for (int idx = tid; idx < 1024; idx += 256) cts[idx] = ctg[idx];
    __syncthreads();

    const int per = NSPAN / NBLK2, rem = NSPAN % NBLK2;   // 34, 185
    const int b   = blockIdx.x;
    const int s0  = b * per + (b < rem ? b : rem);
    const int cnt = per + (b < rem ? 1 : 0);

    auto load_span = [&](int sp, int buf) {
        const int k0 = sp * ASPAN;
        int stride, kl;
        const float* base = seg_base(k0, W1, b1, W2, b2, stride, kl);
        const uint32_t dst0 = sb32 + buf * ASTAGE_B;
#pragma unroll
        for (int i = 0; i < 8; i++) {
            int f = tid + i * 256;                 // 2048 x 16B
            int row = f >> 6, c16 = f & 63;
            cp16(dst0 + f * 16, base + (size_t)row * stride + kl + c16 * 4);
        }
    };

    const int kg = tid >> 2;        // 0..63 : 2 kp = 16B within span
    const int ig = tid & 3;         // 0..3  : 8 output rows
    ull* outp = reinterpret_cast<ull*>(out);

    // prologue: 2 spans in flight
#pragma unroll
    for (int s = 0; s < ASTAGES - 1; s++) {
        if (s < cnt) load_span(s0 + s, s);
        cp_commit();
    }

    for (int it = 0; it < cnt; it++) {
        cp_wait<ASTAGES - 2>();
        __syncthreads();
        {
            int nx = it + ASTAGES - 1;
            if (nx < cnt) load_span(s0 + nx, nx % ASTAGES);
            cp_commit();
        }

        const char* tb = sm + (it % ASTAGES) * ASTAGE_B;
        ull acc[16];
#pragma unroll
        for (int p = 0; p < 16; p++) acc[p] = 0ull;

#pragma unroll
        for (int j = 0; j < 32; j++) {
            ulonglong2 tv = *reinterpret_cast<const ulonglong2*>(tb + j * 1024 + kg * 16);
            const ulonglong2* cp = reinterpret_cast<const ulonglong2*>(cts + j * 32 + ig * 8);
#pragma unroll
            for (int h = 0; h < 4; h++) {
                ulonglong2 cc = cp[h];
                ffma2(acc[(2 * h) * 2 + 0], cc.x, tv.x);
                ffma2(acc[(2 * h) * 2 + 1], cc.x, tv.y);
                ffma2(acc[(2 * h + 1) * 2 + 0], cc.y, tv.x);
                ffma2(acc[(2 * h + 1) * 2 + 1], cc.y, tv.y);
            }
        }

        const size_t kpo = (size_t)(s0 + it) * (ASPAN / 2) + kg * 2;
#pragma unroll
        for (int r = 0; r < 8; r++) {
            int i = ig * 8 + r;
            *reinterpret_cast<ulonglong2*>(outp + (size_t)i * NP + kpo) =
                make_ulonglong2(acc[r * 2], acc[r * 2 + 1]);
        }
    }
}

// ---------------- launch ----------------
extern "C" void kernel_launch(void* const* d_in, const int* in_sizes, int n_in,
                              void* d_out, int out_size) {
    const float* W1 = (const float*)d_in[0];
    const float* b1 = (const float*)d_in[1];
    const float* W2 = (const float*)d_in[2];
    const float* b2 = (const float*)d_in[3];
    float* out = (float*)d_out;

    cudaFuncSetAttribute(gram_kernel,  cudaFuncAttributeMaxDynamicSharedMemorySize,
                         GSTAGES * GSTAGE_B);
    cudaFuncSetAttribute(apply_kernel, cudaFuncAttributeMaxDynamicSharedMemorySize,
                         ASTAGES * ASTAGE_B + 8192);

    gram_kernel<<<NBLK1, 320, GSTAGES * GSTAGE_B>>>(W1, b1, W2, b2);
    coef_kernel<<<1, 1024>>>();
    apply_kernel<<<NBLK2, 256, ASTAGES * ASTAGE_B + 8192>>>(W1, b1, W2, b2, out);
}

// round 5
// speedup vs baseline: 1.1829x; 1.1829x over previous
#include <cuda_runtime.h>
#include <cstdint>

typedef unsigned long long ull;

// ---------------- problem constants ----------------
#define NPART 32
#define L0 (2048*1024)
#define L1 2048
#define L2 (256*2048)
#define L3 256
#define SEG_B0 (L0)              // 2097152
#define SEG_B1 (SEG_B0 + L1)     // 2099200
#define SEG_B2 (SEG_B1 + L2)     // 2623488
#define P_TOT  (SEG_B2 + L3)     // 2623744
#define EPSV 0.1f

// ---- gram pipeline ----
#define GCHUNK 128
#define NCHUNK (P_TOT/GCHUNK)    // 20498
#define GSTAGES 6
#define GSTAGE_B (32*GCHUNK*4)   // 16384 B
#define GSTAGE_OFF 1024
#define GSMEM (GSTAGE_OFF + GSTAGES*GSTAGE_B)   // 99328
#define NBLK1 148
#define NWARP1 10

// ---- apply pipeline ----
#define ASPAN 256
#define NSPAN (P_TOT/ASPAN)      // 10249 exact
#define ASTAGES 3
#define ASTAGE_B (32*ASPAN*4)    // 32768 B
#define ACOEF_OFF 64
#define ASTAGE_OFF 9216
#define ASMEM (ASTAGE_OFF + ASTAGES*ASTAGE_B)   // 107520
#define NBLK2 296
#define NWARP2 8

// ---------------- scratch ----------------
__device__ float  g_Gpart[NBLK1 * NWARP1 * 64];
__device__ float2 g_Cd[1024];        // g_Cd[i*32+j] = (c,c)

__constant__ int c_TBI[NWARP1] = {0,0,0,0,1,1,1,2,2,3};
__constant__ int c_TBJ[NWARP1] = {0,1,2,3,1,2,3,2,3,3};

// ---------------- PTX helpers ----------------
__device__ __forceinline__ void ffma2(ull &d, ull a, ull b) {
    asm("fma.rn.f32x2 %0, %1, %2, %0;" : "+l"(d) : "l"(a), "l"(b));
}
__device__ __forceinline__ void mbar_init(uint32_t mbar, uint32_t cnt) {
    asm volatile("mbarrier.init.shared.b64 [%0], %1;" :: "r"(mbar), "r"(cnt) : "memory");
}
__device__ __forceinline__ void mbar_expect_tx(uint32_t mbar, uint32_t bytes) {
    asm volatile("mbarrier.arrive.expect_tx.shared.b64 _, [%0], %1;"
                 :: "r"(mbar), "r"(bytes) : "memory");
}
__device__ __forceinline__ void mbar_wait(uint32_t mbar, uint32_t phase) {
    asm volatile(
        "{\n\t.reg .pred P;\n\t"
        "WL_%=:\n\t"
        "mbarrier.try_wait.parity.acquire.cta.shared::cta.b64 P, [%0], %1, 0x989680;\n\t"
        "@!P bra WL_%=;\n\t}"
        :: "r"(mbar), "r"(phase) : "memory");
}
// canonical bulk copy form (shared::cluster dst space, local CTA address)
__device__ __forceinline__ void bulk_g2s(uint32_t dst, const void* src,
                                         uint32_t bytes, uint32_t mbar) {
    asm volatile(
        "cp.async.bulk.shared::cluster.global.mbarrier::complete_tx::bytes [%0], [%1], %2, [%3];"
        :: "r"(dst), "l"(src), "r"(bytes), "r"(mbar) : "memory");
}

__device__ __forceinline__ const float* seg_base(int k,
        const float* __restrict__ W1, const float* __restrict__ b1,
        const float* __restrict__ W2, const float* __restrict__ b2,
        int &stride, int &kl) {
    if (k < SEG_B0) { stride = L0; kl = k;          return W1; }
    if (k < SEG_B1) { stride = L1; kl = k - SEG_B0; return b1; }
    if (k < SEG_B2) { stride = L2; kl = k - SEG_B1; return W2; }
    stride = L3; kl = k - SEG_B2; return b2;
}

// ---------------- pass 1: Gram, bulk-copy pipelined SYRK ----------------
__global__ __launch_bounds__(320, 1)
void gram_kernel(const float* __restrict__ W1, const float* __restrict__ b1,
                 const float* __restrict__ W2, const float* __restrict__ b2) {
    extern __shared__ char sm[];
    const uint32_t sb = (uint32_t)__cvta_generic_to_shared(sm);
    const uint32_t mb_full = sb;                 // 6 x 8B at offset 0
    const int tid  = threadIdx.x;
    const int w    = tid >> 5;
    const int lane = tid & 31;
    const int bi = c_TBI[w], bj = c_TBJ[w];

    const int per = NCHUNK / NBLK1, rem = NCHUNK % NBLK1;
    const int b   = blockIdx.x;
    const int c0  = b * per + (b < rem ? b : rem);
    const int cnt = per + (b < rem ? 1 : 0);

    if (tid == 0) {
#pragma unroll
        for (int s = 0; s < GSTAGES; s++) mbar_init(mb_full + s * 8, 1);
    }
    __syncthreads();

    auto load_stage = [&](int n) {                // tid0 only
        const int buf = n % GSTAGES;
        const int k0 = (c0 + n) * GCHUNK;
        int stride, kl;
        const float* base = seg_base(k0, W1, b1, W2, b2, stride, kl);
        const uint32_t full = mb_full + buf * 8;
        mbar_expect_tx(full, GSTAGE_B);
        const uint32_t dst = sb + GSTAGE_OFF + buf * GSTAGE_B;
#pragma unroll
        for (int r = 0; r < 32; r++)
            bulk_g2s(dst + r * 512, base + (size_t)r * stride + kl, 512, full);
    };

    if (tid == 0) {
        for (int n = 0; n < GSTAGES - 1 && n < cnt; n++) load_stage(n);
    }

    ull acc[64];
#pragma unroll
    for (int p = 0; p < 64; p++) acc[p] = 0ull;

    int stg = 0, ph = 0;
    for (int it = 0; it < cnt; it++) {
        __syncthreads();                          // all warps done with it-1
        if (tid == 0) {
            int n = it + GSTAGES - 1;
            if (n < cnt) load_stage(n);           // reloads buffer (it-1)%S : safe
        }
        mbar_wait(mb_full + stg * 8, ph);

        const char* tb = sm + GSTAGE_OFF + stg * GSTAGE_B;
        ulonglong2 av[8];
#pragma unroll
        for (int r = 0; r < 8; r++)
            av[r] = *reinterpret_cast<const ulonglong2*>(tb + (bi * 8 + r) * 512 + lane * 16);
#pragma unroll
        for (int q = 0; q < 8; q++) {
            ulonglong2 bv = *reinterpret_cast<const ulonglong2*>(tb + (bj * 8 + q) * 512 + lane * 16);
#pragma unroll
            for (int r = 0; r < 8; r++) {
                ffma2(acc[r * 8 + q], av[r].x, bv.x);
                ffma2(acc[r * 8 + q], av[r].y, bv.y);
            }
        }
        if (++stg == GSTAGES) { stg = 0; ph ^= 1; }
    }

#pragma unroll
    for (int p = 0; p < 64; p++) {
        float v = __uint_as_float((unsigned)acc[p]) +
                  __uint_as_float((unsigned)(acc[p] >> 32));
        v += __shfl_xor_sync(0xffffffffu, v, 16);
        v += __shfl_xor_sync(0xffffffffu, v, 8);
        v += __shfl_xor_sync(0xffffffffu, v, 4);
        v += __shfl_xor_sync(0xffffffffu, v, 2);
        v += __shfl_xor_sync(0xffffffffu, v, 1);
        if (lane == 0) g_Gpart[(b * NWARP1 + w) * 64 + p] = v;
    }
}

// ---------------- pass 1b: partials -> K -> coefficient table ----------------
__global__ __launch_bounds__(1024, 1)
void coef_kernel() {
    __shared__ float Gs[32][32];
    __shared__ float Ks[32][33];
    __shared__ float Ssh[32];
    const int tid = threadIdx.x;

    if (tid < NWARP1 * 64) {
        float s0 = 0.f, s1 = 0.f, s2 = 0.f, s3 = 0.f;
#pragma unroll 1
        for (int bb = 0; bb < NBLK1; bb += 4) {
            s0 += g_Gpart[(bb + 0) * (NWARP1 * 64) + tid];
            s1 += g_Gpart[(bb + 1) * (NWARP1 * 64) + tid];
            s2 += g_Gpart[(bb + 2) * (NWARP1 * 64) + tid];
            s3 += g_Gpart[(bb + 3) * (NWARP1 * 64) + tid];
        }
        float s = (s0 + s1) + (s2 + s3);
        int w = tid / 64, pr = tid % 64, r = pr / 8, q = pr % 8;
        Gs[c_TBI[w] * 8 + r][c_TBJ[w] * 8 + q] = s;
    }
    __syncthreads();
    {
        int i = tid >> 5, j = tid & 31;
        if ((i >> 3) > (j >> 3)) Gs[i][j] = Gs[j][i];
    }
    __syncthreads();
    {
        int i = tid >> 5, j = tid & 31;
        float d2 = Gs[i][i] + Gs[j][j] - 2.f * Gs[i][j];
        d2 = fmaxf(d2, 0.f);
        Ks[i][j] = expf(-0.5f * d2);
    }
    __syncthreads();
    if (tid < 32) {
        float s = 0.f;
        for (int j = 1; j < 32; j++) s += Ks[tid][j];
        Ssh[tid] = s;
    }
    __syncthreads();
    {
        int i = tid >> 5, j = tid & 31;
        float v = (j >= 1) ? (EPSV / (float)NPART) * Ks[i][j] : 0.f;
        if (j == i) v += 1.f - 3.f * EPSV * Ssh[i] / (float)NPART;
        g_Cd[i * 32 + j] = make_float2(v, v);
    }
}

// ---------------- pass 2: out = C @ theta ----------------
// lane = particle i; warp = 32-k chunk; theta via broadcast LDS.128;
// coef conflict-free LDS.64; smem transpose (XOR swizzle) for coalesced STG.
__global__ __launch_bounds__(256, 2)
void apply_kernel(const float* __restrict__ W1, const float* __restrict__ b1,
                  const float* __restrict__ W2, const float* __restrict__ b2,
                  float* __restrict__ out) {
    extern __shared__ char sm[];
    const uint32_t sb = (uint32_t)__cvta_generic_to_shared(sm);
    const uint32_t mb_full = sb;                              // 3 x 8B
    ull* cs = reinterpret_cast<ull*>(sm + ACOEF_OFF);         // [j*32+i]
    const int tid  = threadIdx.x;
    const int w    = tid >> 5;
    const int lane = tid & 31;

    if (tid == 0) {
#pragma unroll
        for (int s = 0; s < ASTAGES; s++) mbar_init(mb_full + s * 8, 1);
    }
    const ull* cg = reinterpret_cast<const ull*>(g_Cd);
    for (int idx = tid; idx < 1024; idx += 256) {
        int i = idx >> 5, j = idx & 31;
        cs[j * 32 + i] = cg[idx];
    }
    __syncthreads();

    const int per = NSPAN / NBLK2, rem = NSPAN % NBLK2;
    const int b   = blockIdx.x;
    const int s0  = b * per + (b < rem ? b : rem);
    const int cnt = per + (b < rem ? 1 : 0);

    auto load_stage = [&](int n) {                // tid0 only
        const int buf = n % ASTAGES;
        const int k0 = (s0 + n) * ASPAN;
        int stride, kl;
        const float* base = seg_base(k0, W1, b1, W2, b2, stride, kl);
        const uint32_t full = mb_full + buf * 8;
        mbar_expect_tx(full, ASTAGE_B);
        const uint32_t dst = sb + ASTAGE_OFF + buf * ASTAGE_B;
#pragma unroll
        for (int r = 0; r < 32; r++)
            bulk_g2s(dst + r * 1024, base + (size_t)r * stride + kl, 1024, full);
    };

    if (tid == 0) {
        for (int n = 0; n < ASTAGES - 1 && n < cnt; n++) load_stage(n);
    }

    // store-phase thread mapping
    const int sc = lane & 7;            // column octet
    const int sr = 4 * w + (lane >> 3); // row (particle) this thread drains

    int stg = 0, ph = 0;
    for (int it = 0; it < cnt; it++) {
        __syncthreads();                          // everyone past it-1 (incl. drain)
        if (tid == 0) {
            int n = it + ASTAGES - 1;
            if (n < cnt) load_stage(n);           // reloads buffer (it-1)%3 : safe
        }
        mbar_wait(mb_full + stg * 8, ph);

        char* tb  = sm + ASTAGE_OFF + stg * ASTAGE_B;
        const char* tbw = tb + w * 128;           // warp's 32-k chunk
        ull acc[16];
#pragma unroll
        for (int p = 0; p < 16; p++) acc[p] = 0ull;

#pragma unroll
        for (int j = 0; j < 32; j++) {
            const ulonglong2* pv = reinterpret_cast<const ulonglong2*>(tbw + j * 1024);
            ull c = cs[j * 32 + lane];
#pragma unroll
            for (int m = 0; m < 8; m += 2) {
                ulonglong2 v0 = pv[m], v1 = pv[m + 1];
                ffma2(acc[2 * m + 0], c, v0.x);
                ffma2(acc[2 * m + 1], c, v0.y);
                ffma2(acc[2 * m + 2], c, v1.x);
                ffma2(acc[2 * m + 3], c, v1.y);
            }
        }

        __syncthreads();                          // all reads of tb done
        // transpose: lane(=particle i) writes its 32 floats into row i of tb,
        // 16B unit u = w*8+m, XOR-swizzled by (i&7) -> conflict-free phases
        {
            ulonglong2* row = reinterpret_cast<ulonglong2*>(tb + lane * 1024);
#pragma unroll
            for (int m = 0; m < 8; m++) {
                int u = (w * 8 + m) ^ (lane & 7);
                row[u] = make_ulonglong2(acc[2 * m], acc[2 * m + 1]);
            }
        }
        __syncthreads();
        // drain: thread reads row sr, logical units sc+8t, coalesced STG
        {
            const ulonglong2* row = reinterpret_cast<const ulonglong2*>(tb + sr * 1024);
            float* op = out + (size_t)sr * P_TOT + (size_t)(s0 + it) * ASPAN;
#pragma unroll
            for (int t = 0; t < 8; t++) {
                int u = sc + 8 * t;
                ulonglong2 v = row[u ^ (sr & 7)];
                *reinterpret_cast<ulonglong2*>(op + 4 * u) = v;
            }
        }
        if (++stg == ASTAGES) { stg = 0; ph ^= 1; }
    }
}

// ---------------- launch ----------------
extern "C" void kernel_launch(void* const* d_in, const int* in_sizes, int n_in,
                              void* d_out, int out_size) {
    const float* W1 = (const float*)d_in[0];
    const float* b1 = (const float*)d_in[1];
    const float* W2 = (const float*)d_in[2];
    const float* b2 = (const float*)d_in[3];
    float* out = (float*)d_out;

    cudaFuncSetAttribute(gram_kernel,  cudaFuncAttributeMaxDynamicSharedMemorySize, GSMEM);
    cudaFuncSetAttribute(apply_kernel, cudaFuncAttributeMaxDynamicSharedMemorySize, ASMEM);

    gram_kernel<<<NBLK1, 320, GSMEM>>>(W1, b1, W2, b2);
    coef_kernel<<<1, 1024>>>();
    apply_kernel<<<NBLK2, 256, ASMEM>>>(W1, b1, W2, b2, out);
}

// round 6
// speedup vs baseline: 1.3789x; 1.1657x over previous
#include <cuda_runtime.h>
#include <cstdint>

typedef unsigned long long ull;

// ---------------- problem constants ----------------
#define NPART 32
#define L0 (2048*1024)
#define L1 2048
#define L2 (256*2048)
#define L3 256
#define SEG_B0 (L0)              // 2097152
#define SEG_B1 (SEG_B0 + L1)     // 2099200
#define SEG_B2 (SEG_B1 + L2)     // 2623488
#define P_TOT  (SEG_B2 + L3)     // 2623744 = 512*5124 + 256
#define EPSV 0.1f

// chunks of 512 k; last chunk (id 5124) is 256 k (= b2 segment exactly)
#define CH 512
#define NCH 5125
#define ROW_B 2048               // bytes per particle-row per full stage

// ---- gram ----
#define GSTAGES 3
#define GSTAGE_B (32*ROW_B)      // 65536
#define GOFF 1024
#define GSMEM (GOFF + GSTAGES*GSTAGE_B)
#define NBLK1 148
#define NWARP1 10

// ---- apply ----
#define ASTAGES 3
#define ASTAGE_B (32*ROW_B)      // 65536
#define ACOEF_OFF 64
#define AOFF 9216
#define ASMEM (AOFF + ASTAGES*ASTAGE_B)   // 205824
#define NBLK2 148

// ---------------- scratch ----------------
__device__ float  g_Gpart[NBLK1 * NWARP1 * 64];
__device__ float2 g_Cd[1024];        // g_Cd[i*32+j] = (c,c)

__constant__ int c_TBI[NWARP1] = {0,0,0,0,1,1,1,2,2,3};
__constant__ int c_TBJ[NWARP1] = {0,1,2,3,1,2,3,2,3,3};

// ---------------- PTX helpers ----------------
__device__ __forceinline__ void ffma2(ull &d, ull a, ull b) {
    asm("fma.rn.f32x2 %0, %1, %2, %0;" : "+l"(d) : "l"(a), "l"(b));
}
__device__ __forceinline__ void mbar_init(uint32_t mbar, uint32_t cnt) {
    asm volatile("mbarrier.init.shared.b64 [%0], %1;" :: "r"(mbar), "r"(cnt) : "memory");
}
__device__ __forceinline__ void mbar_expect_tx(uint32_t mbar, uint32_t bytes) {
    asm volatile("mbarrier.arrive.expect_tx.shared.b64 _, [%0], %1;"
                 :: "r"(mbar), "r"(bytes) : "memory");
}
__device__ __forceinline__ void mbar_wait(uint32_t mbar, uint32_t phase) {
    asm volatile(
        "{\n\t.reg .pred P;\n\t"
        "WL_%=:\n\t"
        "mbarrier.try_wait.parity.acquire.cta.shared::cta.b64 P, [%0], %1, 0x989680;\n\t"
        "@!P bra WL_%=;\n\t}"
        :: "r"(mbar), "r"(phase) : "memory");
}
__device__ __forceinline__ void bulk_g2s(uint32_t dst, const void* src,
                                         uint32_t bytes, uint32_t mbar) {
    asm volatile(
        "cp.async.bulk.shared::cluster.global.mbarrier::complete_tx::bytes [%0], [%1], %2, [%3];"
        :: "r"(dst), "l"(src), "r"(bytes), "r"(mbar) : "memory");
}

__device__ __forceinline__ const float* seg_base(int k,
        const float* __restrict__ W1, const float* __restrict__ b1,
        const float* __restrict__ W2, const float* __restrict__ b2,
        int &stride, int &kl) {
    if (k < SEG_B0) { stride = L0; kl = k;          return W1; }
    if (k < SEG_B1) { stride = L1; kl = k - SEG_B0; return b1; }
    if (k < SEG_B2) { stride = L2; kl = k - SEG_B1; return W2; }
    stride = L3; kl = k - SEG_B2; return b2;
}

// producer: warp 0 lanes each copy one particle-row of the chunk
__device__ __forceinline__ void load_chunk(int chunk, int buf,
        uint32_t sb, uint32_t dataOff, uint32_t stageB, uint32_t mb_full,
        int lane,
        const float* __restrict__ W1, const float* __restrict__ b1,
        const float* __restrict__ W2, const float* __restrict__ b2) {
    const uint32_t bytes = (chunk == NCH - 1) ? 1024u : 2048u;
    const int k0 = chunk * CH;
    int stride, kl;
    const float* base = seg_base(k0, W1, b1, W2, b2, stride, kl);
    const uint32_t full = mb_full + buf * 8;
    if (lane == 0) mbar_expect_tx(full, bytes * 32);
    __syncwarp();
    bulk_g2s(sb + dataOff + buf * stageB + lane * ROW_B,
             base + (size_t)lane * stride + kl, bytes, full);
}

// ---------------- pass 1: Gram ----------------
__global__ __launch_bounds__(320, 1)
void gram_kernel(const float* __restrict__ W1, const float* __restrict__ b1,
                 const float* __restrict__ W2, const float* __restrict__ b2) {
    extern __shared__ char sm[];
    const uint32_t sb = (uint32_t)__cvta_generic_to_shared(sm);
    const uint32_t mb_full = sb;
    const int tid  = threadIdx.x;
    const int w    = tid >> 5;
    const int lane = tid & 31;
    const int bi = c_TBI[w], bj = c_TBJ[w];

    const int per = NCH / NBLK1, rem = NCH % NBLK1;     // 34, 93
    const int b   = blockIdx.x;
    const int c0  = b * per + (b < rem ? b : rem);
    const int cnt = per + (b < rem ? 1 : 0);

    if (tid == 0) {
#pragma unroll
        for (int s = 0; s < GSTAGES; s++) mbar_init(mb_full + s * 8, 1);
    }
    __syncthreads();

    if (w == 0) {
        for (int n = 0; n < GSTAGES - 1 && n < cnt; n++)
            load_chunk(c0 + n, n, sb, GOFF, GSTAGE_B, mb_full, lane, W1, b1, W2, b2);
    }

    ull acc[64];
#pragma unroll
    for (int p = 0; p < 64; p++) acc[p] = 0ull;

    int stg = 0, ph = 0;
    for (int it = 0; it < cnt; it++) {
        __syncthreads();                       // all warps done with it-1
        if (w == 0) {
            int n = it + GSTAGES - 1;
            if (n < cnt)
                load_chunk(c0 + n, n % GSTAGES, sb, GOFF, GSTAGE_B, mb_full, lane,
                           W1, b1, W2, b2);
        }
        mbar_wait(mb_full + stg * 8, ph);

        const char* tb = sm + GOFF + stg * GSTAGE_B;
        const int niter = (c0 + it == NCH - 1) ? 2 : 4;
        for (int g = 0; g < niter; g++) {
            const char* tg = tb + g * 512 + lane * 16;
            ulonglong2 av[8];
#pragma unroll
            for (int r = 0; r < 8; r++)
                av[r] = *reinterpret_cast<const ulonglong2*>(tg + (bi * 8 + r) * ROW_B);
#pragma unroll
            for (int q = 0; q < 8; q++) {
                ulonglong2 bv = *reinterpret_cast<const ulonglong2*>(tg + (bj * 8 + q) * ROW_B);
#pragma unroll
                for (int r = 0; r < 8; r++) {
                    ffma2(acc[r * 8 + q], av[r].x, bv.x);
                    ffma2(acc[r * 8 + q], av[r].y, bv.y);
                }
            }
        }
        if (++stg == GSTAGES) { stg = 0; ph ^= 1; }
    }

#pragma unroll
    for (int p = 0; p < 64; p++) {
        float v = __uint_as_float((unsigned)acc[p]) +
                  __uint_as_float((unsigned)(acc[p] >> 32));
        v += __shfl_xor_sync(0xffffffffu, v, 16);
        v += __shfl_xor_sync(0xffffffffu, v, 8);
        v += __shfl_xor_sync(0xffffffffu, v, 4);
        v += __shfl_xor_sync(0xffffffffu, v, 2);
        v += __shfl_xor_sync(0xffffffffu, v, 1);
        if (lane == 0) g_Gpart[(b * NWARP1 + w) * 64 + p] = v;
    }
}

// ---------------- pass 1b ----------------
__global__ __launch_bounds__(1024, 1)
void coef_kernel() {
    __shared__ float Gs[32][32];
    __shared__ float Ks[32][33];
    __shared__ float Ssh[32];
    const int tid = threadIdx.x;

    if (tid < NWARP1 * 64) {
        float s0 = 0.f, s1 = 0.f, s2 = 0.f, s3 = 0.f;
#pragma unroll 1
        for (int bb = 0; bb < NBLK1; bb += 4) {
            s0 += g_Gpart[(bb + 0) * (NWARP1 * 64) + tid];
            s1 += g_Gpart[(bb + 1) * (NWARP1 * 64) + tid];
            s2 += g_Gpart[(bb + 2) * (NWARP1 * 64) + tid];
            s3 += g_Gpart[(bb + 3) * (NWARP1 * 64) + tid];
        }
        float s = (s0 + s1) + (s2 + s3);
        int w = tid / 64, pr = tid % 64, r = pr / 8, q = pr % 8;
        Gs[c_TBI[w] * 8 + r][c_TBJ[w] * 8 + q] = s;
    }
    __syncthreads();
    {
        int i = tid >> 5, j = tid & 31;
        if ((i >> 3) > (j >> 3)) Gs[i][j] = Gs[j][i];
    }
    __syncthreads();
    {
        int i = tid >> 5, j = tid & 31;
        float d2 = Gs[i][i] + Gs[j][j] - 2.f * Gs[i][j];
        d2 = fmaxf(d2, 0.f);
        Ks[i][j] = expf(-0.5f * d2);
    }
    __syncthreads();
    if (tid < 32) {
        float s = 0.f;
        for (int j = 1; j < 32; j++) s += Ks[tid][j];
        Ssh[tid] = s;
    }
    __syncthreads();
    {
        int i = tid >> 5, j = tid & 31;
        float v = (j >= 1) ? (EPSV / (float)NPART) * Ks[i][j] : 0.f;
        if (j == i) v += 1.f - 3.f * EPSV * Ssh[i] / (float)NPART;
        g_Cd[i * 32 + j] = make_float2(v, v);
    }
}

// ---------------- pass 2: out = C @ theta ----------------
__global__ __launch_bounds__(256, 1)
void apply_kernel(const float* __restrict__ W1, const float* __restrict__ b1,
                  const float* __restrict__ W2, const float* __restrict__ b2,
                  float* __restrict__ out) {
    extern __shared__ char sm[];
    const uint32_t sb = (uint32_t)__cvta_generic_to_shared(sm);
    const uint32_t mb_full = sb;
    ull* cs = reinterpret_cast<ull*>(sm + ACOEF_OFF);   // [j*32+i]
    const int tid  = threadIdx.x;
    const int w    = tid >> 5;
    const int lane = tid & 31;

    if (tid == 0) {
#pragma unroll
        for (int s = 0; s < ASTAGES; s++) mbar_init(mb_full + s * 8, 1);
    }
    const ull* cg = reinterpret_cast<const ull*>(g_Cd);
    for (int idx = tid; idx < 1024; idx += 256) {
        int i = idx >> 5, j = idx & 31;
        cs[j * 32 + i] = cg[idx];
    }
    __syncthreads();

    const int per = NCH / NBLK2, rem = NCH % NBLK2;
    const int b   = blockIdx.x;
    const int s0  = b * per + (b < rem ? b : rem);
    const int cnt = per + (b < rem ? 1 : 0);

    if (w == 0) {
        for (int n = 0; n < ASTAGES - 1 && n < cnt; n++)
            load_chunk(s0 + n, n, sb, AOFF, ASTAGE_B, mb_full, lane, W1, b1, W2, b2);
    }

    const int sc = lane & 7;            // column octet
    const int sr = 4 * w + (lane >> 3); // particle row this thread drains

    int stg = 0, ph = 0;
    for (int it = 0; it < cnt; it++) {
        __syncthreads();
        if (w == 0) {
            int n = it + ASTAGES - 1;
            if (n < cnt)
                load_chunk(s0 + n, n % ASTAGES, sb, AOFF, ASTAGE_B, mb_full, lane,
                           W1, b1, W2, b2);
        }
        mbar_wait(mb_full + stg * 8, ph);

        char* tb = sm + AOFF + stg * ASTAGE_B;
        const int nsub = (s0 + it == NCH - 1) ? 1 : 2;
        for (int s2 = 0; s2 < nsub; s2++) {
            const char* tbw = tb + s2 * 1024 + w * 128;
            ull acc[16];
#pragma unroll
            for (int p = 0; p < 16; p++) acc[p] = 0ull;

#pragma unroll
            for (int j = 0; j < 32; j++) {
                const ulonglong2* pv = reinterpret_cast<const ulonglong2*>(tbw + j * ROW_B);
                ull c = cs[j * 32 + lane];
#pragma unroll
                for (int m = 0; m < 8; m += 2) {
                    ulonglong2 v0 = pv[m], v1 = pv[m + 1];
                    ffma2(acc[2 * m + 0], c, v0.x);
                    ffma2(acc[2 * m + 1], c, v0.y);
                    ffma2(acc[2 * m + 2], c, v1.x);
                    ffma2(acc[2 * m + 3], c, v1.y);
                }
            }

            __syncthreads();    // all reads of this sub-span done
            {   // transpose into the consumed sub-span region (XOR swizzle)
                ulonglong2* row = reinterpret_cast<ulonglong2*>(tb + lane * ROW_B + s2 * 1024);
#pragma unroll
                for (int m = 0; m < 8; m++) {
                    int u = (w * 8 + m) ^ (lane & 7);
                    row[u] = make_ulonglong2(acc[2 * m], acc[2 * m + 1]);
                }
            }
            __syncthreads();
            {   // drain: coalesced 128B-per-octet stores
                const ulonglong2* row =
                    reinterpret_cast<const ulonglong2*>(tb + sr * ROW_B + s2 * 1024);
                float* op = out + (size_t)sr * P_TOT + (size_t)(s0 + it) * CH + s2 * 256;
#pragma unroll
                for (int t = 0; t < 8; t++) {
                    int u = sc + 8 * t;
                    ulonglong2 v = row[u ^ (sr & 7)];
                    *reinterpret_cast<ulonglong2*>(op + 4 * u) = v;
                }
            }
        }
        if (++stg == ASTAGES) { stg = 0; ph ^= 1; }
    }
}

// ---------------- launch ----------------
extern "C" void kernel_launch(void* const* d_in, const int* in_sizes, int n_in,
                              void* d_out, int out_size) {
    const float* W1 = (const float*)d_in[0];
    const float* b1 = (const float*)d_in[1];
    const float* W2 = (const float*)d_in[2];
    const float* b2 = (const float*)d_in[3];
    float* out = (float*)d_out;

    cudaFuncSetAttribute(gram_kernel,  cudaFuncAttributeMaxDynamicSharedMemorySize, GSMEM);
    cudaFuncSetAttribute(apply_kernel, cudaFuncAttributeMaxDynamicSharedMemorySize, ASMEM);

    gram_kernel<<<NBLK1, 320, GSMEM>>>(W1, b1, W2, b2);
    coef_kernel<<<1, 1024>>>();
    apply_kernel<<<NBLK2, 256, ASMEM>>>(W1, b1, W2, b2, out);
}

// round 7
// speedup vs baseline: 1.4527x; 1.0535x over previous
#include <cuda_runtime.h>
#include <cstdint>

typedef unsigned long long ull;

// ---------------- problem constants ----------------
#define NPART 32
#define L0 (2048*1024)
#define L1 2048
#define L2 (256*2048)
#define L3 256
#define SEG_B0 (L0)              // 2097152
#define SEG_B1 (SEG_B0 + L1)     // 2099200
#define SEG_B2 (SEG_B1 + L2)     // 2623488
#define P_TOT  (SEG_B2 + L3)     // 2623744 = 512*5124 + 256
#define EPSV 0.1f

// chunks of 512 k; last chunk (id 5124) is 256 k
#define CH 512
#define NCH 5125
#define ROW_B 2048

// ---- gram ----
#define GSTAGES 3
#define GSTAGE_B (32*ROW_B)      // 65536
#define GOFF 1024
#define GSMEM (GOFF + GSTAGES*GSTAGE_B)
#define NBLK1 148
#define NWARP1 10

// ---- apply ----
#define ASTAGES 3
#define ASTAGE_B (32*ROW_B)      // 65536
#define AOFF 1024
#define ASMEM (AOFF + ASTAGES*ASTAGE_B)   // 197632
#define NBLK2 148
#define ATHREADS 512

// ---------------- scratch ----------------
__device__ float  g_Gpart[NBLK1 * NWARP1 * 64];
__device__ float  g_Cf[1024];        // g_Cf[j*32+i] = C[i][j] (plain float)

__constant__ int c_TBI[NWARP1] = {0,0,0,0,1,1,1,2,2,3};
__constant__ int c_TBJ[NWARP1] = {0,1,2,3,1,2,3,2,3,3};

// ---------------- PTX helpers ----------------
__device__ __forceinline__ void ffma2(ull &d, ull a, ull b) {
    asm("fma.rn.f32x2 %0, %1, %2, %0;" : "+l"(d) : "l"(a), "l"(b));
}
__device__ __forceinline__ ull dupf(float c) {
    ull r;
    unsigned u = __float_as_uint(c);
    asm("mov.b64 %0, {%1, %1};" : "=l"(r) : "r"(u));
    return r;
}
__device__ __forceinline__ void mbar_init(uint32_t mbar, uint32_t cnt) {
    asm volatile("mbarrier.init.shared.b64 [%0], %1;" :: "r"(mbar), "r"(cnt) : "memory");
}
__device__ __forceinline__ void mbar_expect_tx(uint32_t mbar, uint32_t bytes) {
    asm volatile("mbarrier.arrive.expect_tx.shared.b64 _, [%0], %1;"
                 :: "r"(mbar), "r"(bytes) : "memory");
}
__device__ __forceinline__ void mbar_wait(uint32_t mbar, uint32_t phase) {
    asm volatile(
        "{\n\t.reg .pred P;\n\t"
        "WL_%=:\n\t"
        "mbarrier.try_wait.parity.acquire.cta.shared::cta.b64 P, [%0], %1, 0x989680;\n\t"
        "@!P bra WL_%=;\n\t}"
        :: "r"(mbar), "r"(phase) : "memory");
}
__device__ __forceinline__ void bulk_g2s(uint32_t dst, const void* src,
                                         uint32_t bytes, uint32_t mbar) {
    asm volatile(
        "cp.async.bulk.shared::cluster.global.mbarrier::complete_tx::bytes [%0], [%1], %2, [%3];"
        :: "r"(dst), "l"(src), "r"(bytes), "r"(mbar) : "memory");
}

__device__ __forceinline__ const float* seg_base(int k,
        const float* __restrict__ W1, const float* __restrict__ b1,
        const float* __restrict__ W2, const float* __restrict__ b2,
        int &stride, int &kl) {
    if (k < SEG_B0) { stride = L0; kl = k;          return W1; }
    if (k < SEG_B1) { stride = L1; kl = k - SEG_B0; return b1; }
    if (k < SEG_B2) { stride = L2; kl = k - SEG_B1; return W2; }
    stride = L3; kl = k - SEG_B2; return b2;
}

// producer: warp 0 lanes each copy one particle-row of the chunk
__device__ __forceinline__ void load_chunk(int chunk, int buf,
        uint32_t sb, uint32_t dataOff, uint32_t stageB, uint32_t mb_full,
        int lane,
        const float* __restrict__ W1, const float* __restrict__ b1,
        const float* __restrict__ W2, const float* __restrict__ b2) {
    const uint32_t bytes = (chunk == NCH - 1) ? 1024u : 2048u;
    const int k0 = chunk * CH;
    int stride, kl;
    const float* base = seg_base(k0, W1, b1, W2, b2, stride, kl);
    const uint32_t full = mb_full + buf * 8;
    if (lane == 0) mbar_expect_tx(full, bytes * 32);
    __syncwarp();
    bulk_g2s(sb + dataOff + buf * stageB + lane * ROW_B,
             base + (size_t)lane * stride + kl, bytes, full);
}

// ---------------- pass 1: Gram ----------------
__global__ __launch_bounds__(320, 1)
void gram_kernel(const float* __restrict__ W1, const float* __restrict__ b1,
                 const float* __restrict__ W2, const float* __restrict__ b2) {
    extern __shared__ char sm[];
    const uint32_t sb = (uint32_t)__cvta_generic_to_shared(sm);
    const uint32_t mb_full = sb;
    const int tid  = threadIdx.x;
    const int w    = tid >> 5;
    const int lane = tid & 31;
    const int bi = c_TBI[w], bj = c_TBJ[w];

    const int per = NCH / NBLK1, rem = NCH % NBLK1;
    const int b   = blockIdx.x;
    const int c0  = b * per + (b < rem ? b : rem);
    const int cnt = per + (b < rem ? 1 : 0);

    if (tid == 0) {
#pragma unroll
        for (int s = 0; s < GSTAGES; s++) mbar_init(mb_full + s * 8, 1);
    }
    __syncthreads();

    if (w == 0) {
        for (int n = 0; n < GSTAGES - 1 && n < cnt; n++)
            load_chunk(c0 + n, n, sb, GOFF, GSTAGE_B, mb_full, lane, W1, b1, W2, b2);
    }

    ull acc[64];
#pragma unroll
    for (int p = 0; p < 64; p++) acc[p] = 0ull;

    int stg = 0, ph = 0;
    for (int it = 0; it < cnt; it++) {
        __syncthreads();
        if (w == 0) {
            int n = it + GSTAGES - 1;
            if (n < cnt)
                load_chunk(c0 + n, n % GSTAGES, sb, GOFF, GSTAGE_B, mb_full, lane,
                           W1, b1, W2, b2);
        }
        mbar_wait(mb_full + stg * 8, ph);

        const char* tb = sm + GOFF + stg * GSTAGE_B;
        const int niter = (c0 + it == NCH - 1) ? 2 : 4;
        for (int g = 0; g < niter; g++) {
            const char* tg = tb + g * 512 + lane * 16;
            ulonglong2 av[8];
#pragma unroll
            for (int r = 0; r < 8; r++)
                av[r] = *reinterpret_cast<const ulonglong2*>(tg + (bi * 8 + r) * ROW_B);
#pragma unroll
            for (int q = 0; q < 8; q++) {
                ulonglong2 bv = *reinterpret_cast<const ulonglong2*>(tg + (bj * 8 + q) * ROW_B);
#pragma unroll
                for (int r = 0; r < 8; r++) {
                    ffma2(acc[r * 8 + q], av[r].x, bv.x);
                    ffma2(acc[r * 8 + q], av[r].y, bv.y);
                }
            }
        }
        if (++stg == GSTAGES) { stg = 0; ph ^= 1; }
    }

#pragma unroll
    for (int p = 0; p < 64; p++) {
        float v = __uint_as_float((unsigned)acc[p]) +
                  __uint_as_float((unsigned)(acc[p] >> 32));
        v += __shfl_xor_sync(0xffffffffu, v, 16);
        v += __shfl_xor_sync(0xffffffffu, v, 8);
        v += __shfl_xor_sync(0xffffffffu, v, 4);
        v += __shfl_xor_sync(0xffffffffu, v, 2);
        v += __shfl_xor_sync(0xffffffffu, v, 1);
        if (lane == 0) g_Gpart[(b * NWARP1 + w) * 64 + p] = v;
    }
}

// ---------------- pass 1b ----------------
__global__ __launch_bounds__(1024, 1)
void coef_kernel() {
    __shared__ float Gs[32][32];
    __shared__ float Ks[32][33];
    __shared__ float Ssh[32];
    const int tid = threadIdx.x;

    if (tid < NWARP1 * 64) {
        float s0 = 0.f, s1 = 0.f, s2 = 0.f, s3 = 0.f;
#pragma unroll 1
        for (int bb = 0; bb < NBLK1; bb += 4) {
            s0 += g_Gpart[(bb + 0) * (NWARP1 * 64) + tid];
            s1 += g_Gpart[(bb + 1) * (NWARP1 * 64) + tid];
            s2 += g_Gpart[(bb + 2) * (NWARP1 * 64) + tid];
            s3 += g_Gpart[(bb + 3) * (NWARP1 * 64) + tid];
        }
        float s = (s0 + s1) + (s2 + s3);
        int w = tid / 64, pr = tid % 64, r = pr / 8, q = pr % 8;
        Gs[c_TBI[w] * 8 + r][c_TBJ[w] * 8 + q] = s;
    }
    __syncthreads();
    {
        int i = tid >> 5, j = tid & 31;
        if ((i >> 3) > (j >> 3)) Gs[i][j] = Gs[j][i];
    }
    __syncthreads();
    {
        int i = tid >> 5, j = tid & 31;
        float d2 = Gs[i][i] + Gs[j][j] - 2.f * Gs[i][j];
        d2 = fmaxf(d2, 0.f);
        Ks[i][j] = expf(-0.5f * d2);
    }
    __syncthreads();
    if (tid < 32) {
        float s = 0.f;
        for (int j = 1; j < 32; j++) s += Ks[tid][j];
        Ssh[tid] = s;
    }
    __syncthreads();
    {
        int i = tid >> 5, j = tid & 31;
        float v = (j >= 1) ? (EPSV / (float)NPART) * Ks[i][j] : 0.f;
        if (j == i) v += 1.f - 3.f * EPSV * Ssh[i] / (float)NPART;
        g_Cf[j * 32 + i] = v;
    }
}

// ---------------- pass 2: out = C @ theta ----------------
// 16 warps; warp w = k in [32w, 32w+32); lane = particle i.
// Coefficient row C[i][:] lives in 32 registers per lane.
__global__ __launch_bounds__(ATHREADS, 1)
void apply_kernel(const float* __restrict__ W1, const float* __restrict__ b1,
                  const float* __restrict__ W2, const float* __restrict__ b2,
                  float* __restrict__ out) {
    extern __shared__ char sm[];
    const uint32_t sb = (uint32_t)__cvta_generic_to_shared(sm);
    const uint32_t mb_full = sb;
    const int tid  = threadIdx.x;
    const int w    = tid >> 5;
    const int lane = tid & 31;

    if (tid == 0) {
#pragma unroll
        for (int s = 0; s < ASTAGES; s++) mbar_init(mb_full + s * 8, 1);
    }

    // per-lane coefficient row: cf[j] = C[lane][j]
    float cf[32];
#pragma unroll
    for (int j = 0; j < 32; j++) cf[j] = g_Cf[j * 32 + lane];
    __syncthreads();

    const int per = NCH / NBLK2, rem = NCH % NBLK2;
    const int b   = blockIdx.x;
    const int s0  = b * per + (b < rem ? b : rem);
    const int cnt = per + (b < rem ? 1 : 0);

    if (w == 0) {
        for (int n = 0; n < ASTAGES - 1 && n < cnt; n++)
            load_chunk(s0 + n, n, sb, AOFF, ASTAGE_B, mb_full, lane, W1, b1, W2, b2);
    }

    const int sc = tid & 15;            // drain: column 16B-unit group
    const int sr = (tid >> 4) & 31;     // drain: particle row

    int stg = 0, ph = 0;
    for (int it = 0; it < cnt; it++) {
        __syncthreads();                          // drain of it-1 done everywhere
        if (w == 0) {
            int n = it + ASTAGES - 1;
            if (n < cnt)
                load_chunk(s0 + n, n % ASTAGES, sb, AOFF, ASTAGE_B, mb_full, lane,
                           W1, b1, W2, b2);
        }
        mbar_wait(mb_full + stg * 8, ph);

        char* tb = sm + AOFF + stg * ASTAGE_B;
        const bool last = (s0 + it == NCH - 1);   // 256-k tail chunk
        const bool active = !last || (w < 8);

        ull acc[16];
#pragma unroll
        for (int p = 0; p < 16; p++) acc[p] = 0ull;

        if (active) {
            const char* tbw = tb + w * 128;       // warp's 32-k window
#pragma unroll
            for (int j = 0; j < 32; j++) {
                const ulonglong2* pv = reinterpret_cast<const ulonglong2*>(tbw + j * ROW_B);
                ull c = dupf(cf[j]);
#pragma unroll
                for (int m = 0; m < 8; m += 2) {
                    ulonglong2 v0 = pv[m], v1 = pv[m + 1];
                    ffma2(acc[2 * m + 0], c, v0.x);
                    ffma2(acc[2 * m + 1], c, v0.y);
                    ffma2(acc[2 * m + 2], c, v1.x);
                    ffma2(acc[2 * m + 3], c, v1.y);
                }
            }
        }

        __syncthreads();                          // all reads of tb done
        if (active) {                             // transpose (XOR swizzle in octet)
            ulonglong2* row = reinterpret_cast<ulonglong2*>(tb + lane * ROW_B);
#pragma unroll
            for (int m = 0; m < 8; m++) {
                int u = (w * 8 + m) ^ (lane & 7);
                row[u] = make_ulonglong2(acc[2 * m], acc[2 * m + 1]);
            }
        }
        __syncthreads();
        {   // drain: 16 threads per row, 256B-coalesced stores
            const int umax = last ? 64 : 128;
            const ulonglong2* row = reinterpret_cast<const ulonglong2*>(tb + sr * ROW_B);
            float* op = out + (size_t)sr * P_TOT + (size_t)(s0 + it) * CH;
#pragma unroll
            for (int t = 0; t < 8; t++) {
                int u = sc + 16 * t;
                if (u < umax) {
                    int base8 = u & ~7;
                    ulonglong2 v = row[base8 + ((u & 7) ^ (sr & 7))];
                    *reinterpret_cast<ulonglong2*>(op + 4 * u) = v;
                }
            }
        }
        if (++stg == ASTAGES) { stg = 0; ph ^= 1; }
    }
}

// ---------------- launch ----------------
extern "C" void kernel_launch(void* const* d_in, const int* in_sizes, int n_in,
                              void* d_out, int out_size) {
    const float* W1 = (const float*)d_in[0];
    const float* b1 = (const float*)d_in[1];
    const float* W2 = (const float*)d_in[2];
    const float* b2 = (const float*)d_in[3];
    float* out = (float*)d_out;

    cudaFuncSetAttribute(gram_kernel,  cudaFuncAttributeMaxDynamicSharedMemorySize, GSMEM);
    cudaFuncSetAttribute(apply_kernel, cudaFuncAttributeMaxDynamicSharedMemorySize, ASMEM);

    gram_kernel<<<NBLK1, 320, GSMEM>>>(W1, b1, W2, b2);
    coef_kernel<<<1, 1024>>>();
    apply_kernel<<<NBLK2, ATHREADS, ASMEM>>>(W1, b1, W2, b2, out);
}

// round 8
// speedup vs baseline: 1.4986x; 1.0316x over previous
#include <cuda_runtime.h>
#include <cstdint>

typedef unsigned long long ull;

// ---------------- problem constants ----------------
#define NPART 32
#define L0 (2048*1024)
#define L1 2048
#define L2 (256*2048)
#define L3 256
#define SEG_B0 (L0)              // 2097152
#define SEG_B1 (SEG_B0 + L1)     // 2099200
#define SEG_B2 (SEG_B1 + L2)     // 2623488
#define P_TOT  (SEG_B2 + L3)     // 2623744
#define EPSV 0.1f

// ---- gram: chunks of 512 k (last = 256 k) ----
#define GCH 512
#define GNCH 5125
#define GROW_B 2048
#define GSTAGES 3
#define GSTAGE_B (32*GROW_B)     // 65536
#define GOFF 1024
#define GSMEM (GOFF + GSTAGES*GSTAGE_B)
#define NBLK1 148
#define NWARP1 10
#define GPW 9                    // producer warp (highest priority)

// ---- apply: chunks of 256 k (exact: 10249 chunks) ----
#define ACH 256
#define ANCH (P_TOT/ACH)         // 10249, no tail
#define AROW_B 1024
#define ASTAGES 3
#define ASTAGE_B (32*AROW_B)     // 32768
#define AOFF 1024
#define ASMEM (AOFF + ASTAGES*ASTAGE_B)   // 99328 -> 2 CTAs/SM
#define NBLK2 296
#define APW 7                    // producer warp

// ---------------- scratch ----------------
__device__ float g_Gpart[NBLK1 * NWARP1 * 64];
__device__ float g_Cf[1024];         // g_Cf[j*32+i] = C[i][j]

__constant__ int c_TBI[NWARP1] = {0,0,0,0,1,1,1,2,2,3};
__constant__ int c_TBJ[NWARP1] = {0,1,2,3,1,2,3,2,3,3};

// ---------------- PTX helpers ----------------
__device__ __forceinline__ void ffma2(ull &d, ull a, ull b) {
    asm("fma.rn.f32x2 %0, %1, %2, %0;" : "+l"(d) : "l"(a), "l"(b));
}
__device__ __forceinline__ ull dupf(float c) {
    ull r;
    unsigned u = __float_as_uint(c);
    asm("mov.b64 %0, {%1, %1};" : "=l"(r) : "r"(u));
    return r;
}
__device__ __forceinline__ void mbar_init(uint32_t mbar, uint32_t cnt) {
    asm volatile("mbarrier.init.shared.b64 [%0], %1;" :: "r"(mbar), "r"(cnt) : "memory");
}
__device__ __forceinline__ void mbar_expect_tx(uint32_t mbar, uint32_t bytes) {
    asm volatile("mbarrier.arrive.expect_tx.shared.b64 _, [%0], %1;"
                 :: "r"(mbar), "r"(bytes) : "memory");
}
__device__ __forceinline__ void mbar_wait(uint32_t mbar, uint32_t phase) {
    asm volatile(
        "{\n\t.reg .pred P;\n\t"
        "WL_%=:\n\t"
        "mbarrier.try_wait.parity.acquire.cta.shared::cta.b64 P, [%0], %1, 0x989680;\n\t"
        "@!P bra WL_%=;\n\t}"
        :: "r"(mbar), "r"(phase) : "memory");
}
__device__ __forceinline__ void bulk_g2s(uint32_t dst, const void* src,
                                         uint32_t bytes, uint32_t mbar) {
    asm volatile(
        "cp.async.bulk.shared::cluster.global.mbarrier::complete_tx::bytes [%0], [%1], %2, [%3];"
        :: "r"(dst), "l"(src), "r"(bytes), "r"(mbar) : "memory");
}

__device__ __forceinline__ const float* seg_base(int k,
        const float* __restrict__ W1, const float* __restrict__ b1,
        const float* __restrict__ W2, const float* __restrict__ b2,
        int &stride, int &kl) {
    if (k < SEG_B0) { stride = L0; kl = k;          return W1; }
    if (k < SEG_B1) { stride = L1; kl = k - SEG_B0; return b1; }
    if (k < SEG_B2) { stride = L2; kl = k - SEG_B1; return W2; }
    stride = L3; kl = k - SEG_B2; return b2;
}

// ---------------- pass 1: Gram ----------------
__global__ __launch_bounds__(320, 1)
void gram_kernel(const float* __restrict__ W1, const float* __restrict__ b1,
                 const float* __restrict__ W2, const float* __restrict__ b2) {
    extern __shared__ char sm[];
    const uint32_t sb = (uint32_t)__cvta_generic_to_shared(sm);
    const uint32_t mb_full = sb;
    const int tid  = threadIdx.x;
    const int w    = tid >> 5;
    const int lane = tid & 31;
    const int bi = c_TBI[w], bj = c_TBJ[w];

    const int per = GNCH / NBLK1, rem = GNCH % NBLK1;
    const int b   = blockIdx.x;
    const int c0  = b * per + (b < rem ? b : rem);
    const int cnt = per + (b < rem ? 1 : 0);

    if (tid == 0) {
#pragma unroll
        for (int s = 0; s < GSTAGES; s++) mbar_init(mb_full + s * 8, 1);
    }
    __syncthreads();

    auto load_chunk = [&](int n) {                // producer warp, lane-parallel
        const int chunk = c0 + n;
        const int buf = n % GSTAGES;
        const uint32_t bytes = (chunk == GNCH - 1) ? 1024u : 2048u;
        int stride, kl;
        const float* base = seg_base(chunk * GCH, W1, b1, W2, b2, stride, kl);
        const uint32_t full = mb_full + buf * 8;
        if (lane == 0) mbar_expect_tx(full, bytes * 32);
        __syncwarp();
        bulk_g2s(sb + GOFF + buf * GSTAGE_B + lane * GROW_B,
                 base + (size_t)lane * stride + kl, bytes, full);
    };

    if (w == GPW) {
        for (int n = 0; n < GSTAGES - 1 && n < cnt; n++) load_chunk(n);
    }

    ull acc[64];
#pragma unroll
    for (int p = 0; p < 64; p++) acc[p] = 0ull;

    int stg = 0, ph = 0;
    for (int it = 0; it < cnt; it++) {
        __syncthreads();
        if (w == GPW) {
            int n = it + GSTAGES - 1;
            if (n < cnt) load_chunk(n);
        }
        mbar_wait(mb_full + stg * 8, ph);

        const char* tb = sm + GOFF + stg * GSTAGE_B;
        const int niter = (c0 + it == GNCH - 1) ? 2 : 4;
        for (int g = 0; g < niter; g++) {
            const char* tg = tb + g * 512 + lane * 16;
            ulonglong2 av[8];
#pragma unroll
            for (int r = 0; r < 8; r++)
                av[r] = *reinterpret_cast<const ulonglong2*>(tg + (bi * 8 + r) * GROW_B);
            // software-pipelined bv stream
            ulonglong2 bv = *reinterpret_cast<const ulonglong2*>(tg + (bj * 8) * GROW_B);
#pragma unroll
            for (int q = 0; q < 8; q++) {
                ulonglong2 bvn;
                if (q < 7)
                    bvn = *reinterpret_cast<const ulonglong2*>(tg + (bj * 8 + q + 1) * GROW_B);
#pragma unroll
                for (int r = 0; r < 8; r++) {
                    ffma2(acc[r * 8 + q], av[r].x, bv.x);
                    ffma2(acc[r * 8 + q], av[r].y, bv.y);
                }
                bv = bvn;
            }
        }
        if (++stg == GSTAGES) { stg = 0; ph ^= 1; }
    }

#pragma unroll
    for (int p = 0; p < 64; p++) {
        float v = __uint_as_float((unsigned)acc[p]) +
                  __uint_as_float((unsigned)(acc[p] >> 32));
        v += __shfl_xor_sync(0xffffffffu, v, 16);
        v += __shfl_xor_sync(0xffffffffu, v, 8);
        v += __shfl_xor_sync(0xffffffffu, v, 4);
        v += __shfl_xor_sync(0xffffffffu, v, 2);
        v += __shfl_xor_sync(0xffffffffu, v, 1);
        if (lane == 0) g_Gpart[(b * NWARP1 + w) * 64 + p] = v;
    }
}

// ---------------- pass 1b ----------------
__global__ __launch_bounds__(1024, 1)
void coef_kernel() {
    __shared__ float Gs[32][32];
    __shared__ float Ks[32][33];
    __shared__ float Ssh[32];
    const int tid = threadIdx.x;

    if (tid < NWARP1 * 64) {
        float s0 = 0.f, s1 = 0.f, s2 = 0.f, s3 = 0.f;
#pragma unroll 1
        for (int bb = 0; bb < NBLK1; bb += 4) {
            s0 += g_Gpart[(bb + 0) * (NWARP1 * 64) + tid];
            s1 += g_Gpart[(bb + 1) * (NWARP1 * 64) + tid];
            s2 += g_Gpart[(bb + 2) * (NWARP1 * 64) + tid];
            s3 += g_Gpart[(bb + 3) * (NWARP1 * 64) + tid];
        }
        float s = (s0 + s1) + (s2 + s3);
        int w = tid / 64, pr = tid % 64, r = pr / 8, q = pr % 8;
        Gs[c_TBI[w] * 8 + r][c_TBJ[w] * 8 + q] = s;
    }
    __syncthreads();
    {
        int i = tid >> 5, j = tid & 31;
        if ((i >> 3) > (j >> 3)) Gs[i][j] = Gs[j][i];
    }
    __syncthreads();
    {
        int i = tid >> 5, j = tid & 31;
        float d2 = Gs[i][i] + Gs[j][j] - 2.f * Gs[i][j];
        d2 = fmaxf(d2, 0.f);
        Ks[i][j] = expf(-0.5f * d2);
    }
    __syncthreads();
    if (tid < 32) {
        float s = 0.f;
        for (int j = 1; j < 32; j++) s += Ks[tid][j];
        Ssh[tid] = s;
    }
    __syncthreads();
    {
        int i = tid >> 5, j = tid & 31;
        float v = (j >= 1) ? (EPSV / (float)NPART) * Ks[i][j] : 0.f;
        if (j == i) v += 1.f - 3.f * EPSV * Ssh[i] / (float)NPART;
        g_Cf[j * 32 + i] = v;
    }
}

// ---------------- pass 2: out = C @ theta ----------------
// 2 CTAs/SM, 8 warps each; warp w = k in [32w, 32w+32) of a 256-k chunk;
// lane = particle i; coef row in registers.
__global__ __launch_bounds__(256, 2)
void apply_kernel(const float* __restrict__ W1, const float* __restrict__ b1,
                  const float* __restrict__ W2, const float* __restrict__ b2,
                  float* __restrict__ out) {
    extern __shared__ char sm[];
    const uint32_t sb = (uint32_t)__cvta_generic_to_shared(sm);
    const uint32_t mb_full = sb;
    const int tid  = threadIdx.x;
    const int w    = tid >> 5;
    const int lane = tid & 31;

    if (tid == 0) {
#pragma unroll
        for (int s = 0; s < ASTAGES; s++) mbar_init(mb_full + s * 8, 1);
    }

    float cf[32];
#pragma unroll
    for (int j = 0; j < 32; j++) cf[j] = g_Cf[j * 32 + lane];
    __syncthreads();

    const int per = ANCH / NBLK2, rem = ANCH % NBLK2;
    const int b   = blockIdx.x;
    const int s0  = b * per + (b < rem ? b : rem);
    const int cnt = per + (b < rem ? 1 : 0);

    auto load_chunk = [&](int n) {                // producer warp, lane-parallel
        const int buf = n % ASTAGES;
        int stride, kl;
        const float* base = seg_base((s0 + n) * ACH, W1, b1, W2, b2, stride, kl);
        const uint32_t full = mb_full + buf * 8;
        if (lane == 0) mbar_expect_tx(full, 32 * 1024u);
        __syncwarp();
        bulk_g2s(sb + AOFF + buf * ASTAGE_B + lane * AROW_B,
                 base + (size_t)lane * stride + kl, 1024u, full);
    };

    if (w == APW) {
        for (int n = 0; n < ASTAGES - 1 && n < cnt; n++) load_chunk(n);
    }

    const int sc = tid & 7;             // drain: unit-in-octet
    const int sr = tid >> 3;            // drain: particle row (0..31)

    int stg = 0, ph = 0;
    for (int it = 0; it < cnt; it++) {
        __syncthreads();
        if (w == APW) {
            int n = it + ASTAGES - 1;
            if (n < cnt) load_chunk(n);
        }
        mbar_wait(mb_full + stg * 8, ph);

        char* tb = sm + AOFF + stg * ASTAGE_B;
        const char* tbw = tb + w * 128;           // warp's 32-k window

        ull acc[16];
#pragma unroll
        for (int p = 0; p < 16; p++) acc[p] = 0ull;

#pragma unroll
        for (int j = 0; j < 32; j++) {
            const ulonglong2* pv = reinterpret_cast<const ulonglong2*>(tbw + j * AROW_B);
            ull c = dupf(cf[j]);
#pragma unroll
            for (int m = 0; m < 8; m += 2) {
                ulonglong2 v0 = pv[m], v1 = pv[m + 1];
                ffma2(acc[2 * m + 0], c, v0.x);
                ffma2(acc[2 * m + 1], c, v0.y);
                ffma2(acc[2 * m + 2], c, v1.x);
                ffma2(acc[2 * m + 3], c, v1.y);
            }
        }

        __syncthreads();                          // all reads of tb done
        {   // transpose: lane=particle row, XOR swizzle within octet
            ulonglong2* row = reinterpret_cast<ulonglong2*>(tb + lane * AROW_B);
#pragma unroll
            for (int m = 0; m < 8; m++) {
                int u = (w * 8 + m) ^ (lane & 7);
                row[u] = make_ulonglong2(acc[2 * m], acc[2 * m + 1]);
            }
        }
        __syncthreads();
        {   // drain: 8 threads per particle row, 128B-coalesced per octet
            const ulonglong2* row = reinterpret_cast<const ulonglong2*>(tb + sr * AROW_B);
            float* op = out + (size_t)sr * P_TOT + (size_t)(s0 + it) * ACH;
#pragma unroll
            for (int t = 0; t < 8; t++) {
                int u = sc + 8 * t;
                ulonglong2 v = row[(u & ~7) + ((u & 7) ^ (sr & 7))];
                *reinterpret_cast<ulonglong2*>(op + 4 * u) = v;
            }
        }
        if (++stg == ASTAGES) { stg = 0; ph ^= 1; }
    }
}

// ---------------- launch ----------------
extern "C" void kernel_launch(void* const* d_in, const int* in_sizes, int n_in,
                              void* d_out, int out_size) {
    const float* W1 = (const float*)d_in[0];
    const float* b1 = (const float*)d_in[1];
    const float* W2 = (const float*)d_in[2];
    const float* b2 = (const float*)d_in[3];
    float* out = (float*)d_out;

    cudaFuncSetAttribute(gram_kernel,  cudaFuncAttributeMaxDynamicSharedMemorySize, GSMEM);
    cudaFuncSetAttribute(apply_kernel, cudaFuncAttributeMaxDynamicSharedMemorySize, ASMEM);

    gram_kernel<<<NBLK1, 320, GSMEM>>>(W1, b1, W2, b2);
    coef_kernel<<<1, 1024>>>();
    apply_kernel<<<NBLK2, 256, ASMEM>>>(W1, b1, W2, b2, out);
}